// round 4
// baseline (speedup 1.0000x reference)
#include <cuda_runtime.h>
#include <math.h>

#define BB 8
#define NN 256
#define KK 128
#define HH 32
#define EMB 768
#define FD 768

// out layout (float32, concatenated in reference-return order)
#define GAB_ELEMS   (BB*HH*NN*NN)      // 16777216
#define MEF_ELEMS   (BB*NN*EMB)        // 1572864

// scratch (no cudaMalloc allowed)
__device__ float g_sumef[BB * NN * KK];
__device__ int   g_pad[BB * NN];

// ---------------------------------------------------------------------------
// padding mask: node padded iff all 768 features == 0
// ---------------------------------------------------------------------------
__global__ void mask_kernel(const float* __restrict__ nf) {
    int bn = blockIdx.x;
    const float* p = nf + (size_t)bn * FD;
    int nz = 0;
    for (int q = threadIdx.x; q < FD; q += blockDim.x)
        nz |= (p[q] != 0.0f);
    int any = __syncthreads_or(nz);
    if (threadIdx.x == 0) g_pad[bn] = (any == 0) ? 1 : 0;
}

// ---------------------------------------------------------------------------
// fused main kernel: one block per (b, i)
//   phase 0: delta_pos out + dist -> t[j] = exp(-d)
//   phase 1: for 8 k-tiles: generate ef[16k x 256j] in smem (exp computed once),
//            local j-sum for sum_edge_features, SGEMM vs w1 (smem-resident)
//   phase 2: gelu -> hidden smem [256 x 129], GEMM2 vs w2, masked write of gab
// ---------------------------------------------------------------------------

// smem float offsets
#define OFF_W1   0          // 16384 floats (phase 1)
#define OFF_EF   16384      // 16*256 = 4096 floats (phase 1)
#define OFF_HID  0          // 256*129 = 33024 floats (phase 2, overlaps W1/EF)
#define OFF_W2   33024      // 4096
#define OFF_T    37120      // 256
#define OFF_KEEP 37376      // 256
#define OFF_SUM  37632      // 128
#define OFF_MS   37760      // 128
#define OFF_BS   37888      // 128
#define OFF_B1   38016      // 128
#define OFF_B2   38144      // 32
#define SMEM_FLOATS 38176   // 152704 bytes

__global__ __launch_bounds__(512, 1)
void main_kernel(const float* __restrict__ pos,
                 const float* __restrict__ means,
                 const float* __restrict__ betas,
                 const float* __restrict__ w1,
                 const float* __restrict__ b1,
                 const float* __restrict__ w2,
                 const float* __restrict__ b2,
                 float* __restrict__ gab,
                 float* __restrict__ dpos)
{
    extern __shared__ float sm[];
    float* w1s  = sm + OFF_W1;
    float* efs  = sm + OFF_EF;
    float* hid  = sm + OFF_HID;
    float* w2s  = sm + OFF_W2;
    float* ts   = sm + OFF_T;
    float* keep = sm + OFF_KEEP;
    float* sums = sm + OFF_SUM;
    float* ms   = sm + OFF_MS;
    float* bs   = sm + OFF_BS;
    float* b1s  = sm + OFF_B1;
    float* b2s  = sm + OFF_B2;

    const int i   = blockIdx.x;
    const int b   = blockIdx.y;
    const int tid = threadIdx.x;

    // ---- cooperative loads of weights into smem ----
    {
        const float4* src = (const float4*)w1;
        float4* dst = (float4*)w1s;
#pragma unroll
        for (int q = 0; q < 8; q++) dst[tid + 512 * q] = src[tid + 512 * q];
    }
    {
        const float4* src = (const float4*)w2;
        float4* dst = (float4*)w2s;
        dst[tid] = src[tid];
        dst[tid + 512] = src[tid + 512];
    }
    if (tid < 128) {
        ms[tid]  = means[tid];
        bs[tid]  = betas[tid];
        b1s[tid] = b1[tid];
        sums[tid] = 0.0f;
    }
    if (tid < 32) b2s[tid] = b2[tid];

    // ---- phase 0: delta_pos, dist, t, keep ----
    const float pix = pos[(b * NN + i) * 3 + 0];
    const float piy = pos[(b * NN + i) * 3 + 1];
    const float piz = pos[(b * NN + i) * 3 + 2];
    if (tid < NN) {
        int j = tid;
        float pjx = pos[(b * NN + j) * 3 + 0];
        float pjy = pos[(b * NN + j) * 3 + 1];
        float pjz = pos[(b * NN + j) * 3 + 2];
        float dx = pix - pjx, dy = piy - pjy, dz = piz - pjz;
        size_t dbase = (((size_t)(b * NN + i)) * NN + j) * 3;
        dpos[dbase + 0] = dx;
        dpos[dbase + 1] = dy;
        dpos[dbase + 2] = dz;
        float r = dx * dx + dy * dy + dz * dz;
        float d = (r > 0.0f) ? sqrtf(r) : 0.0f;
        ts[j] = expf(-d);                 // ALPHA = 1, CUT_LO = 0
        keep[j] = g_pad[b * NN + j] ? 0.0f : 1.0f;
    }
    __syncthreads();

    const int tx = tid & 15;     // h-group: h = tx*8 .. tx*8+7
    const int ty = tid >> 4;     // j-group: j = ty*8 .. ty*8+7
    const int gj = tid & 255;    // generation: this thread's j
    const int ub = (tid >> 8) * 8; // generation: rows ub..ub+7
    const int w  = tid >> 5;     // warp id (0..15)
    const int lane = tid & 31;

    float acc[8][8];
#pragma unroll
    for (int a = 0; a < 8; a++)
#pragma unroll
        for (int c = 0; c < 8; c++) acc[a][c] = 0.0f;

    // ---- phase 1: 8 k-tiles of 16 ----
    const float tj = ts[gj];
    for (int kt = 0; kt < 8; kt++) {
        // generate ef tile [u=16][j=256], one exp per element
#pragma unroll
        for (int q = 0; q < 8; q++) {
            int u = ub + q;
            int k = kt * 16 + u;
            float diff = tj - ms[k];
            efs[u * 256 + gj] = expf(-bs[k] * diff * diff);
        }
        __syncthreads();

        // masked j-sum for this tile's 16 k rows: warp w owns row u=w
        {
            float s = 0.0f;
#pragma unroll
            for (int p = 0; p < 8; p++) {
                int j = lane + 32 * p;
                s += efs[w * 256 + j] * keep[j];
            }
#pragma unroll
            for (int off = 16; off; off >>= 1)
                s += __shfl_down_sync(0xffffffffu, s, off);
            if (lane == 0) sums[kt * 16 + w] = s;
        }

        // SGEMM: acc[j][h] += ef[j][k] * w1[k][h]
#pragma unroll
        for (int u = 0; u < 16; u++) {
            float4 a0 = *(const float4*)&efs[u * 256 + ty * 8];
            float4 a1 = *(const float4*)&efs[u * 256 + ty * 8 + 4];
            float4 q0 = *(const float4*)&w1s[(kt * 16 + u) * 128 + tx * 8];
            float4 q1 = *(const float4*)&w1s[(kt * 16 + u) * 128 + tx * 8 + 4];
            float av[8] = {a0.x, a0.y, a0.z, a0.w, a1.x, a1.y, a1.z, a1.w};
            float bv[8] = {q0.x, q0.y, q0.z, q0.w, q1.x, q1.y, q1.z, q1.w};
#pragma unroll
            for (int jr = 0; jr < 8; jr++)
#pragma unroll
                for (int hc = 0; hc < 8; hc++)
                    acc[jr][hc] = fmaf(av[jr], bv[hc], acc[jr][hc]);
        }
        __syncthreads();   // before next tile overwrites efs
    }

    // ---- phase 2: gelu -> hidden smem (overlaps w1s/efs; all reads done) ----
#pragma unroll
    for (int jr = 0; jr < 8; jr++) {
        int j = ty * 8 + jr;
#pragma unroll
        for (int hc = 0; hc < 8; hc++) {
            int h = tx * 8 + hc;
            float x = acc[jr][hc] + b1s[h];
            float g = 0.5f * x * (1.0f + erff(x * 0.70710678118654752f));
            hid[j * 129 + h] = g;
        }
    }
    __syncthreads();

    // sum_edge_features out
    if (tid < 128)
        g_sumef[((size_t)(b * NN + i)) * 128 + tid] = sums[tid];

    // GEMM2: bias[j][m] = sum_h hid[j][h] * w2[h][m] + b2[m]
    {
        int j   = tid & 255;
        int grp = tid >> 8;      // 0..1
        int m0  = grp * 16;
        float acc2[16];
#pragma unroll
        for (int q = 0; q < 16; q++) acc2[q] = b2s[m0 + q];

#pragma unroll 4
        for (int h = 0; h < 128; h++) {
            float hv = hid[j * 129 + h];
            const float4* wr = (const float4*)&w2s[h * 32 + m0];
            float4 r0 = wr[0], r1 = wr[1], r2 = wr[2], r3 = wr[3];
            acc2[0]  = fmaf(hv, r0.x, acc2[0]);
            acc2[1]  = fmaf(hv, r0.y, acc2[1]);
            acc2[2]  = fmaf(hv, r0.z, acc2[2]);
            acc2[3]  = fmaf(hv, r0.w, acc2[3]);
            acc2[4]  = fmaf(hv, r1.x, acc2[4]);
            acc2[5]  = fmaf(hv, r1.y, acc2[5]);
            acc2[6]  = fmaf(hv, r1.z, acc2[6]);
            acc2[7]  = fmaf(hv, r1.w, acc2[7]);
            acc2[8]  = fmaf(hv, r2.x, acc2[8]);
            acc2[9]  = fmaf(hv, r2.y, acc2[9]);
            acc2[10] = fmaf(hv, r2.z, acc2[10]);
            acc2[11] = fmaf(hv, r2.w, acc2[11]);
            acc2[12] = fmaf(hv, r3.x, acc2[12]);
            acc2[13] = fmaf(hv, r3.y, acc2[13]);
            acc2[14] = fmaf(hv, r3.z, acc2[14]);
            acc2[15] = fmaf(hv, r3.w, acc2[15]);
        }

        bool pad = (keep[j] == 0.0f);
#pragma unroll
        for (int q = 0; q < 16; q++) {
            int m = m0 + q;
            size_t o = (((size_t)(b * HH + m)) * NN + i) * NN + j;
            gab[o] = pad ? -1e20f : acc2[q];
        }
    }
}

// ---------------------------------------------------------------------------
// merge_edge_features = sum_ef @ ew + eb   ([2048,128] @ [128,768])
// 128 blocks x 16 rows, 256 threads, 3 cols per thread
// ---------------------------------------------------------------------------
__global__ __launch_bounds__(256)
void merge_kernel(const float* __restrict__ ew,
                  const float* __restrict__ eb,
                  float* __restrict__ out)
{
    __shared__ float sef[16 * 128];
    const int r0  = blockIdx.x * 16;
    const int tid = threadIdx.x;

#pragma unroll
    for (int q = 0; q < 8; q++)
        sef[tid + 256 * q] = g_sumef[(size_t)r0 * 128 + tid + 256 * q];
    __syncthreads();

    float acc[3][16];
#pragma unroll
    for (int q = 0; q < 3; q++) {
        float e = eb[q * 256 + tid];
#pragma unroll
        for (int r = 0; r < 16; r++) acc[q][r] = e;
    }

    for (int k = 0; k < 128; k++) {
        float v0 = ew[(size_t)k * EMB + tid];
        float v1 = ew[(size_t)k * EMB + 256 + tid];
        float v2 = ew[(size_t)k * EMB + 512 + tid];
#pragma unroll
        for (int r = 0; r < 16; r++) {
            float s = sef[r * 128 + k];
            acc[0][r] = fmaf(s, v0, acc[0][r]);
            acc[1][r] = fmaf(s, v1, acc[1][r]);
            acc[2][r] = fmaf(s, v2, acc[2][r]);
        }
    }

#pragma unroll
    for (int r = 0; r < 16; r++)
#pragma unroll
        for (int q = 0; q < 3; q++)
            out[(size_t)(r0 + r) * EMB + q * 256 + tid] = acc[q][r];
}

// ---------------------------------------------------------------------------
extern "C" void kernel_launch(void* const* d_in, const int* in_sizes, int n_in,
                              void* d_out, int out_size) {
    const float* nf    = (const float*)d_in[0];
    const float* pos   = (const float*)d_in[1];
    const float* means = (const float*)d_in[2];
    const float* betas = (const float*)d_in[3];
    const float* w1    = (const float*)d_in[4];
    const float* b1    = (const float*)d_in[5];
    const float* w2    = (const float*)d_in[6];
    const float* b2    = (const float*)d_in[7];
    const float* ew    = (const float*)d_in[8];
    const float* eb    = (const float*)d_in[9];

    float* out  = (float*)d_out;
    float* gab  = out;
    float* mef  = out + GAB_ELEMS;
    float* dpos = out + GAB_ELEMS + MEF_ELEMS;

    cudaFuncSetAttribute(main_kernel,
                         cudaFuncAttributeMaxDynamicSharedMemorySize,
                         SMEM_FLOATS * (int)sizeof(float));

    mask_kernel<<<BB * NN, 128>>>(nf);

    dim3 grid(NN, BB);
    main_kernel<<<grid, 512, SMEM_FLOATS * sizeof(float)>>>(
        pos, means, betas, w1, b1, w2, b2, gab, dpos);

    merge_kernel<<<(BB * NN) / 16, 256>>>(ew, eb, mef);
}

// round 7
// speedup vs baseline: 1.7736x; 1.7736x over previous
#include <cuda_runtime.h>
#include <cuda_bf16.h>
#include <math.h>
#include <stdint.h>

#define BB 8
#define NN 256
#define KK 128
#define HH 32
#define EMB 768
#define FD 768

#define GAB_ELEMS   (BB*HH*NN*NN)      // 16777216
#define MEF_ELEMS   (BB*NN*EMB)        // 1572864

// scratch (no cudaMalloc allowed)
__device__ float g_sumef[BB * NN * KK];
__device__ int   g_pad[BB * NN];

// ---------------------------------------------------------------------------
// SMEM layout (bytes). u32 strides with stride%32==4 -> conflict-free
// fragment LDS (bank = (4*g + c4) % 32 per lane).
//   A   : ef chunk bf16-pairs [256 j][36]  (32 kpairs of this chunk + 4 pad)
//   B1  : w1^T bf16-pairs     [128 h][68]  (64 kpairs + 4 pad)  FULL K
//   B2  : w2^T bf16-pairs     [ 32 m][68]  (64 hpairs + 4 pad)
//   G   : gelu bf16-pairs     [256 j][68]  aliases A (hi) / B1 (lo)
//   CST : C2 staging fp32     [256 j][37]  aliases G (after GEMM2)
// ---------------------------------------------------------------------------
#define AHI    0         // 36864
#define ALO    36864     // -> 73728
#define B1HI   73728     // 34816 -> 108544
#define B1LO   108544    // 34816 -> 143360
#define B2HI   143360    // 8704  -> 152064
#define B2LO   152064    // 8704  -> 160768
#define GHI    0         // 69632  (<= 73728, over A)
#define GLO    73728     // 69632 -> 143360 (exactly over B1)
#define CSTO   0         // 37888  (over Ghi, after GEMM2)
#define TSOF   160768    // 1024
#define KEEPO  161792    // 1024
#define SPART  162816    // 4096 (512 x float2)
#define SMEM_TOTAL 166912

// ---------------------------------------------------------------------------
__device__ __forceinline__ void mma_bf16(float* c, uint32_t a0, uint32_t a1,
                                         uint32_t a2, uint32_t a3,
                                         uint32_t b0, uint32_t b1) {
    asm volatile(
        "mma.sync.aligned.m16n8k16.row.col.f32.bf16.bf16.f32 "
        "{%0,%1,%2,%3}, {%4,%5,%6,%7}, {%8,%9}, {%0,%1,%2,%3};"
        : "+f"(c[0]), "+f"(c[1]), "+f"(c[2]), "+f"(c[3])
        : "r"(a0), "r"(a1), "r"(a2), "r"(a3), "r"(b0), "r"(b1));
}

// split e0,e1 into bf16 hi/lo pairs; packed reg = (elem k low 16, k+1 high)
__device__ __forceinline__ void splitpack(float e0, float e1,
                                          uint32_t& hi, uint32_t& lo) {
    __nv_bfloat16 h0 = __float2bfloat16_rn(e0);
    __nv_bfloat16 h1 = __float2bfloat16_rn(e1);
    float h0f = __bfloat162float(h0);
    float h1f = __bfloat162float(h1);
    __nv_bfloat16 l0 = __float2bfloat16_rn(e0 - h0f);
    __nv_bfloat16 l1 = __float2bfloat16_rn(e1 - h1f);
    hi = ((uint32_t)__bfloat16_as_ushort(h1) << 16) | __bfloat16_as_ushort(h0);
    lo = ((uint32_t)__bfloat16_as_ushort(l1) << 16) | __bfloat16_as_ushort(l0);
}

__device__ __forceinline__ float gelu_exact(float x) {
    return 0.5f * x * (1.0f + erff(x * 0.70710678118654752f));
}

// ---------------------------------------------------------------------------
__global__ void mask_kernel(const float* __restrict__ nf) {
    int bn = blockIdx.x;
    const float* p = nf + (size_t)bn * FD;
    int nz = 0;
    for (int q = threadIdx.x; q < FD; q += blockDim.x)
        nz |= (p[q] != 0.0f);
    int any = __syncthreads_or(nz);
    if (threadIdx.x == 0) g_pad[bn] = (any == 0) ? 1 : 0;
}

// ---------------------------------------------------------------------------
__global__ __launch_bounds__(512, 1)
void main_kernel(const float* __restrict__ pos,
                 const float* __restrict__ means,
                 const float* __restrict__ betas,
                 const float* __restrict__ w1,
                 const float* __restrict__ b1,
                 const float* __restrict__ w2,
                 const float* __restrict__ b2,
                 float* __restrict__ gab,
                 float* __restrict__ dpos)
{
    extern __shared__ char smem[];
    uint32_t* Ahi  = (uint32_t*)(smem + AHI);
    uint32_t* Alo  = (uint32_t*)(smem + ALO);
    uint32_t* Bhi  = (uint32_t*)(smem + B1HI);
    uint32_t* Blo  = (uint32_t*)(smem + B1LO);
    uint32_t* Ghi  = (uint32_t*)(smem + GHI);
    uint32_t* Glo  = (uint32_t*)(smem + GLO);
    uint32_t* B2hi = (uint32_t*)(smem + B2HI);
    uint32_t* B2lo = (uint32_t*)(smem + B2LO);
    float*    Cst  = (float*)(smem + CSTO);
    float*    ts   = (float*)(smem + TSOF);
    float*    keep = (float*)(smem + KEEPO);
    float2*   spart = (float2*)(smem + SPART);

    const int i    = blockIdx.x;
    const int b    = blockIdx.y;
    const int tid  = threadIdx.x;
    const int w    = tid >> 5;
    const int lane = tid & 31;
    const int g    = lane >> 2;   // fragment row group
    const int c4   = lane & 3;    // fragment col group

    // ---- B1 = w1^T as bf16 hi/lo pairs (64 kpairs, stride 68) ----
    {
        int h  = tid & 127;
        int kg = tid >> 7;                 // 0..3
#pragma unroll
        for (int q = 0; q < 16; q++) {
            int kp = kg * 16 + q;          // 0..63
            float v0 = w1[(2 * kp) * 128 + h];
            float v1 = w1[(2 * kp + 1) * 128 + h];
            uint32_t hi, lo;
            splitpack(v0, v1, hi, lo);
            Bhi[h * 68 + kp] = hi;
            Blo[h * 68 + kp] = lo;
        }
    }
    // ---- B2 = w2^T as bf16 hi/lo pairs (64 hpairs, stride 68) ----
    {
        int m  = tid & 31;
        int hg = tid >> 5;                 // 0..15
#pragma unroll
        for (int q = 0; q < 4; q++) {
            int hp = hg * 4 + q;           // 0..63
            float v0 = w2[(2 * hp) * 32 + m];
            float v1 = w2[(2 * hp + 1) * 32 + m];
            uint32_t hi, lo;
            splitpack(v0, v1, hi, lo);
            B2hi[m * 68 + hp] = hi;
            B2lo[m * 68 + hp] = lo;
        }
    }

    // ---- phase 0: dpos, t[j], keep[j] ----
    const float pix = pos[(b * NN + i) * 3 + 0];
    const float piy = pos[(b * NN + i) * 3 + 1];
    const float piz = pos[(b * NN + i) * 3 + 2];
    if (tid < NN) {
        int j = tid;
        float pjx = pos[(b * NN + j) * 3 + 0];
        float pjy = pos[(b * NN + j) * 3 + 1];
        float pjz = pos[(b * NN + j) * 3 + 2];
        float dx = pix - pjx, dy = piy - pjy, dz = piz - pjz;
        size_t dbase = (((size_t)(b * NN + i)) * NN + j) * 3;
        dpos[dbase + 0] = dx;
        dpos[dbase + 1] = dy;
        dpos[dbase + 2] = dz;
        float r = dx * dx + dy * dy + dz * dz;
        float d = (r > 0.0f) ? sqrtf(r) : 0.0f;
        ts[j] = expf(-d);               // ALPHA=1, CUT_LO=0
        keep[j] = g_pad[b * NN + j] ? 0.0f : 1.0f;
    }
    __syncthreads();

    // ================= GEMM1 accumulators ==================================
    const int wj = w & 3;    // j-tile: 64 rows at wj*64
    const int wh = w >> 2;   // h-tile: 32 cols at wh*32

    float acc[4][4][4];
#pragma unroll
    for (int mi = 0; mi < 4; mi++)
#pragma unroll
        for (int ni = 0; ni < 4; ni++)
#pragma unroll
            for (int q = 0; q < 4; q++) acc[mi][ni][q] = 0.0f;

    // ================= K-chunk loop: generate A chunk + GEMM1 ==============
    for (int kc = 0; kc < 2; kc++) {
        // generate ef chunk [256 j][64 k] (32 kpairs), masked partial sums
        {
            int kp = tid & 31;           // local k-pair 0..31
            int jg = tid >> 5;           // 0..15, 16 j each
            int k0 = kc * 64 + 2 * kp;
            float mk0 = means[k0],     mk1 = means[k0 + 1];
            float bk0 = betas[k0],     bk1 = betas[k0 + 1];
            float s0 = 0.0f, s1 = 0.0f;
#pragma unroll 4
            for (int q = 0; q < 16; q++) {
                int j = jg * 16 + q;
                float t  = ts[j];
                float kj = keep[j];
                float d0 = t - mk0;
                float d1 = t - mk1;
                float e0 = expf(-bk0 * d0 * d0);
                float e1 = expf(-bk1 * d1 * d1);
                s0 += e0 * kj;
                s1 += e1 * kj;
                uint32_t hi, lo;
                splitpack(e0, e1, hi, lo);
                Ahi[j * 36 + kp] = hi;
                Alo[j * 36 + kp] = lo;
            }
            spart[tid] = make_float2(s0, s1);
        }
        __syncthreads();

        // fold masked j-sums for this chunk's 64 k -> g_sumef
        if (tid < 64) {
            int kp = tid >> 1, c = tid & 1;
            float s = 0.0f;
#pragma unroll
            for (int jg = 0; jg < 16; jg++) {
                float2 v = spart[jg * 32 + kp];
                s += c ? v.y : v.x;
            }
            g_sumef[((size_t)(b * NN + i)) * 128 + kc * 64 + tid] = s;
        }

        // GEMM1 partial: 4 k-steps of 16
#pragma unroll
        for (int ks = 0; ks < 4; ks++) {
            int kp0 = ks * 8 + c4;            // local pair 0..27
            int kb  = kc * 32 + kp0;          // global pair for B
            uint32_t bh0[4], bh1[4], bl0[4], bl1[4];
#pragma unroll
            for (int ni = 0; ni < 4; ni++) {
                int n = wh * 32 + ni * 8 + g;
                bh0[ni] = Bhi[n * 68 + kb];
                bh1[ni] = Bhi[n * 68 + kb + 4];
                bl0[ni] = Blo[n * 68 + kb];
                bl1[ni] = Blo[n * 68 + kb + 4];
            }
#pragma unroll
            for (int mi = 0; mi < 4; mi++) {
                int r0 = wj * 64 + mi * 16 + g;
                int r1 = r0 + 8;
                uint32_t ah0 = Ahi[r0 * 36 + kp0];
                uint32_t ah1 = Ahi[r1 * 36 + kp0];
                uint32_t ah2 = Ahi[r0 * 36 + kp0 + 4];
                uint32_t ah3 = Ahi[r1 * 36 + kp0 + 4];
                uint32_t al0 = Alo[r0 * 36 + kp0];
                uint32_t al1 = Alo[r1 * 36 + kp0];
                uint32_t al2 = Alo[r0 * 36 + kp0 + 4];
                uint32_t al3 = Alo[r1 * 36 + kp0 + 4];
#pragma unroll
                for (int ni = 0; ni < 4; ni++) {
                    mma_bf16(acc[mi][ni], ah0, ah1, ah2, ah3, bh0[ni], bh1[ni]);
                    mma_bf16(acc[mi][ni], al0, al1, al2, al3, bh0[ni], bh1[ni]);
                    mma_bf16(acc[mi][ni], ah0, ah1, ah2, ah3, bl0[ni], bl1[ni]);
                }
            }
        }
        __syncthreads();   // before next chunk overwrites A / before G aliases
    }

    // ---- epilogue1: +b1, exact GELU, split/pack into G (aliases A/B1) ----
    {
        float b1r0[4], b1r1[4];
#pragma unroll
        for (int ni = 0; ni < 4; ni++) {
            int h0 = wh * 32 + ni * 8 + c4 * 2;
            b1r0[ni] = b1[h0];
            b1r1[ni] = b1[h0 + 1];
        }
#pragma unroll
        for (int mi = 0; mi < 4; mi++) {
            int r0 = wj * 64 + mi * 16 + g;
            int r1 = r0 + 8;
#pragma unroll
            for (int ni = 0; ni < 4; ni++) {
                int hp = wh * 16 + ni * 4 + c4;
                float g00 = gelu_exact(acc[mi][ni][0] + b1r0[ni]);
                float g01 = gelu_exact(acc[mi][ni][1] + b1r1[ni]);
                float g10 = gelu_exact(acc[mi][ni][2] + b1r0[ni]);
                float g11 = gelu_exact(acc[mi][ni][3] + b1r1[ni]);
                uint32_t hi, lo;
                splitpack(g00, g01, hi, lo);
                Ghi[r0 * 68 + hp] = hi;  Glo[r0 * 68 + hp] = lo;
                splitpack(g10, g11, hi, lo);
                Ghi[r1 * 68 + hp] = hi;  Glo[r1 * 68 + hp] = lo;
            }
        }
    }
    __syncthreads();

    // ================= GEMM2: C2[256j][32m] = G @ w2 ========================
    float acc2[4][4];
#pragma unroll
    for (int ni = 0; ni < 4; ni++)
#pragma unroll
        for (int q = 0; q < 4; q++) acc2[ni][q] = 0.0f;

    const int jt = w * 16;
#pragma unroll
    for (int ks = 0; ks < 8; ks++) {
        int kp0 = ks * 8 + c4;
        int r0 = jt + g;
        int r1 = r0 + 8;
        uint32_t ah0 = Ghi[r0 * 68 + kp0];
        uint32_t ah1 = Ghi[r1 * 68 + kp0];
        uint32_t ah2 = Ghi[r0 * 68 + kp0 + 4];
        uint32_t ah3 = Ghi[r1 * 68 + kp0 + 4];
        uint32_t al0 = Glo[r0 * 68 + kp0];
        uint32_t al1 = Glo[r1 * 68 + kp0];
        uint32_t al2 = Glo[r0 * 68 + kp0 + 4];
        uint32_t al3 = Glo[r1 * 68 + kp0 + 4];
#pragma unroll
        for (int ni = 0; ni < 4; ni++) {
            int n = ni * 8 + g;
            uint32_t bh0 = B2hi[n * 68 + kp0];
            uint32_t bh1 = B2hi[n * 68 + kp0 + 4];
            uint32_t bl0 = B2lo[n * 68 + kp0];
            uint32_t bl1 = B2lo[n * 68 + kp0 + 4];
            mma_bf16(acc2[ni], ah0, ah1, ah2, ah3, bh0, bh1);
            mma_bf16(acc2[ni], al0, al1, al2, al3, bh0, bh1);
            mma_bf16(acc2[ni], ah0, ah1, ah2, ah3, bl0, bl1);
        }
    }

    __syncthreads();   // all G reads done; Cst may alias G

    // ---- epilogue2: +b2 into staging ----
#pragma unroll
    for (int ni = 0; ni < 4; ni++) {
        int m0 = ni * 8 + c4 * 2;
        float e0 = b2[m0], e1 = b2[m0 + 1];
        int r0 = jt + g, r1 = r0 + 8;
        Cst[r0 * 37 + m0]     = acc2[ni][0] + e0;
        Cst[r0 * 37 + m0 + 1] = acc2[ni][1] + e1;
        Cst[r1 * 37 + m0]     = acc2[ni][2] + e0;
        Cst[r1 * 37 + m0 + 1] = acc2[ni][3] + e1;
    }
    __syncthreads();

    // ---- coalesced gab stores: gab[b][m][i][j] ----
    {
        size_t base = (((size_t)b * HH) * NN + i) * NN;
#pragma unroll
        for (int it = 0; it < 16; it++) {
            int idx = it * 512 + tid;
            int m = idx >> 8;
            int j = idx & 255;
            float v = Cst[j * 37 + m];
            gab[base + (size_t)m * NN * NN + j] =
                (keep[j] == 0.0f) ? -1e20f : v;
        }
    }
}

// ---------------------------------------------------------------------------
// merge_edge_features = sum_ef @ ew + eb   ([2048,128] @ [128,768])
// ---------------------------------------------------------------------------
__global__ __launch_bounds__(256)
void merge_kernel(const float* __restrict__ ew,
                  const float* __restrict__ eb,
                  float* __restrict__ out)
{
    __shared__ float sef[16 * 128];
    const int r0  = blockIdx.x * 16;
    const int tid = threadIdx.x;

#pragma unroll
    for (int q = 0; q < 8; q++)
        sef[tid + 256 * q] = g_sumef[(size_t)r0 * 128 + tid + 256 * q];
    __syncthreads();

    float acc[3][16];
#pragma unroll
    for (int q = 0; q < 3; q++) {
        float e = eb[q * 256 + tid];
#pragma unroll
        for (int r = 0; r < 16; r++) acc[q][r] = e;
    }

    for (int k = 0; k < 128; k++) {
        float v0 = ew[(size_t)k * EMB + tid];
        float v1 = ew[(size_t)k * EMB + 256 + tid];
        float v2 = ew[(size_t)k * EMB + 512 + tid];
#pragma unroll
        for (int r = 0; r < 16; r++) {
            float s = sef[r * 128 + k];
            acc[0][r] = fmaf(s, v0, acc[0][r]);
            acc[1][r] = fmaf(s, v1, acc[1][r]);
            acc[2][r] = fmaf(s, v2, acc[2][r]);
        }
    }

#pragma unroll
    for (int r = 0; r < 16; r++)
#pragma unroll
        for (int q = 0; q < 3; q++)
            out[(size_t)(r0 + r) * EMB + q * 256 + tid] = acc[q][r];
}

// ---------------------------------------------------------------------------
extern "C" void kernel_launch(void* const* d_in, const int* in_sizes, int n_in,
                              void* d_out, int out_size) {
    const float* nf    = (const float*)d_in[0];
    const float* pos   = (const float*)d_in[1];
    const float* means = (const float*)d_in[2];
    const float* betas = (const float*)d_in[3];
    const float* w1    = (const float*)d_in[4];
    const float* b1    = (const float*)d_in[5];
    const float* w2    = (const float*)d_in[6];
    const float* b2    = (const float*)d_in[7];
    const float* ew    = (const float*)d_in[8];
    const float* eb    = (const float*)d_in[9];

    float* out  = (float*)d_out;
    float* gab  = out;
    float* mef  = out + GAB_ELEMS;
    float* dpos = out + GAB_ELEMS + MEF_ELEMS;

    cudaFuncSetAttribute(main_kernel,
                         cudaFuncAttributeMaxDynamicSharedMemorySize,
                         SMEM_TOTAL);

    mask_kernel<<<BB * NN, 128>>>(nf);

    dim3 grid(NN, BB);
    main_kernel<<<grid, 512, SMEM_TOTAL>>>(
        pos, means, betas, w1, b1, w2, b2, gab, dpos);

    merge_kernel<<<(BB * NN) / 16, 256>>>(ew, eb, mef);
}